// round 14
// baseline (speedup 1.0000x reference)
#include <cuda_runtime.h>
#include <cuda_bf16.h>
#include <cstdint>
#include <math.h>

#define NDIM 8192
#define RANK 64
#define BM 256
#define BKC 32
#define KQ (NDIM / 4)          // 2048 per K-split
#define NCH (KQ / BKC)         // 64 chunks per CTA
#define QTHREADS 256
#define ROWB 80                // bf16 smem row stride (bytes), conflict-free
#define A_TILE (BM * ROWB)     // 20480
#define B_TILE (RANK * ROWB)   // 5120
#define QSMEM (1024 + 2 * (A_TILE + B_TILE))
#define NCTAS 256

// ---- device scratch (allocation-free rule) ----
__device__ double g_acc[3];                     // [0]=E1, [1]=quad_U, [2]=quad_V
__device__ unsigned int g_done;                 // CTA completion counter
__device__ float  g_Vt[NDIM * RANK];            // V^T fp32 [8192,64]
__device__ __nv_bfloat16 g_Bu[RANK * NDIM];     // U^T bf16 [64,8192] (MMA B)
__device__ __nv_bfloat16 g_Bv[RANK * NDIM];     // V   bf16 [64,8192] (MMA B)
__device__ __nv_bfloat16 g_Ub16[NDIM * RANK];   // U    bf16 [8192,64] (e1)
__device__ __nv_bfloat16 g_Vt16[NDIM * RANK];   // V^T  bf16 [8192,64] (e1)

__device__ __forceinline__ uint32_t smem_u32(const void* p) {
    uint32_t a;
    asm("{ .reg .u64 t; cvta.to.shared.u64 t, %1; cvt.u32.u64 %0, t; }"
        : "=r"(a) : "l"(p));
    return a;
}

// ======================= prep (fused, grid.z selects) =======================
__global__ void prep_kernel(const float* __restrict__ V,
                            const float* __restrict__ U) {
    __shared__ float tile[32][33];
    if (blockIdx.z == 0) {
        int x = blockIdx.x * 32 + threadIdx.x;   // n
        int y = blockIdx.y * 32 + threadIdx.y;   // r
        float v = V[(size_t)y * NDIM + x];
        tile[threadIdx.y][threadIdx.x] = v;
        g_Bv[(size_t)y * NDIM + x] = __float2bfloat16(v);
        __syncthreads();
        int n = blockIdx.x * 32 + threadIdx.y;
        int r = blockIdx.y * 32 + threadIdx.x;
        float tv = tile[threadIdx.x][threadIdx.y];
        g_Vt[(size_t)n * RANK + r] = tv;
        g_Vt16[(size_t)n * RANK + r] = __float2bfloat16(tv);
        if (blockIdx.x == 0 && blockIdx.y == 0 && threadIdx.y == 0 &&
            threadIdx.x < 3)
            g_acc[threadIdx.x] = 0.0;
    } else {
        int i0 = blockIdx.x * 32, r0 = blockIdx.y * 32;
        float u = U[(size_t)(i0 + threadIdx.y) * RANK + r0 + threadIdx.x];
        tile[threadIdx.y][threadIdx.x] = u;
        g_Ub16[(size_t)(i0 + threadIdx.y) * RANK + r0 + threadIdx.x] =
            __float2bfloat16(u);
        __syncthreads();
        g_Bu[(size_t)(r0 + threadIdx.y) * NDIM + i0 + threadIdx.x] =
            __float2bfloat16(tile[threadIdx.x][threadIdx.y]);
    }
}

// ===== fused quad (HMMA bf16, BM=256 B-amortized) + pipelined e1 =====
// 8 warps; warp wid owns TWO m16 tiles (rows wid*32..+31) x full N=64 —
// B fragments reused across both tiles (halves B-ldmatrix traffic).
// BKC=32, K-split=4, 64 chunks/CTA, 1 sync/chunk, 2 CTAs/SM.
// A staged in two halves per iteration (each covered by a 32-MMA phase);
// e1 pipelined with indices prefetched one chunk ahead.
__global__ __launch_bounds__(QTHREADS, 2) void fused_kernel(
    const float* __restrict__ S_U, const float* __restrict__ U,
    const float* __restrict__ S_V, const float* __restrict__ vals,
    const int* __restrict__ rows, const int* __restrict__ cols,
    const float* __restrict__ sigma, float* __restrict__ out, int nobs) {
    extern __shared__ char dynsmem[];
    __shared__ float wsum[QTHREADS / 32];
    __shared__ float esum[QTHREADS / 32];

    const int t = threadIdx.x;
    const int wid = t >> 5, lane = t & 31;

    const float* S;
    const __nv_bfloat16* Bg;
    const float* Xf;
    int slot;
    if (blockIdx.z == 0) { S = S_U; Bg = g_Bu; Xf = U;    slot = 1; }
    else                 { S = S_V; Bg = g_Bv; Xf = g_Vt; slot = 2; }
    const int i0 = blockIdx.x * BM;
    const size_t kbase = (size_t)blockIdx.y * KQ;
    const int ctaid = blockIdx.x + 32 * blockIdx.y + 128 * blockIdx.z; // 0..255

    // e1: warp covers 512 obs; 8 per chunk = 2 batches of 4 (8 lanes/obs).
    const int e1base = ctaid * 4096 + wid * 512;
    const int lg = lane >> 3;
    const int ls = lane & 7;

    uint32_t base = (smem_u32(dynsmem) + 1023u) & ~1023u;
    uint32_t buf0 = base;
    uint32_t buf1 = base + (A_TILE + B_TILE);

    // ---- staging bases: A rows (t>>3)+32p, cols (t&7)*4; B rows t>>2 ----
    const float* a_base = S + (size_t)(i0 + (t >> 3)) * NDIM + kbase +
                          (t & 7) * 4;
    const uint32_t a_st = (uint32_t)(t >> 3) * ROWB + (t & 7) * 8;
    const __nv_bfloat16* b_base = Bg + (size_t)(t >> 2) * NDIM + kbase +
                                  (t & 3) * 8;
    const uint32_t b_st = (uint32_t)(t >> 2) * ROWB + (t & 3) * 16;

    // ldmatrix lane offsets (R8-validated)
    const uint32_t a_lm = (uint32_t)(wid * 32 + (lane & 15)) * ROWB +
                          (lane & 16);
    const uint32_t b_lm = (uint32_t)((lane & 7) + ((lane & 16) >> 1)) * ROWB +
                          ((lane & 8) << 1);

    float acc[2][8][4];
    #pragma unroll
    for (int mi = 0; mi < 2; mi++)
        #pragma unroll
        for (int tn = 0; tn < 8; tn++)
            #pragma unroll
            for (int q = 0; q < 4; q++) acc[mi][tn][q] = 0.f;

    float e1sum = 0.f;
    float4 rA[4];
    uint4  rB;
    int er1, ec1, er2, ec2;
    float ev1, ev2;
    uint4 ua, vb;

#define LOAD_A(k0, h) do {                                                    \
    _Pragma("unroll") for (int p = 0; p < 4; p++)                             \
        rA[p] = __ldcs((const float4*)(a_base + (k0) +                        \
                                       (size_t)((h) * 4 + p) * 32 * NDIM));   \
} while (0)

#define LOAD_B(k0) do { rB = *(const uint4*)(b_base + (k0)); } while (0)

#define STORE_A(buf, h) do {                                                  \
    _Pragma("unroll") for (int p = 0; p < 4; p++) {                           \
        uint32_t lo, hi;                                                      \
        asm("cvt.rn.bf16x2.f32 %0, %1, %2;" : "=r"(lo)                        \
            : "f"(rA[p].y), "f"(rA[p].x));                                    \
        asm("cvt.rn.bf16x2.f32 %0, %1, %2;" : "=r"(hi)                        \
            : "f"(rA[p].w), "f"(rA[p].z));                                    \
        asm volatile("st.shared.v2.b32 [%0], {%1, %2};"                       \
                     :: "r"((buf) + a_st + ((h) * 4 + p) * (32 * ROWB)),      \
                        "r"(lo), "r"(hi));                                    \
    }                                                                         \
} while (0)

#define STORE_B(buf) do {                                                     \
    asm volatile("st.shared.v4.b32 [%0], {%1, %2, %3, %4};"                   \
                 :: "r"((buf) + A_TILE + b_st), "r"(rB.x), "r"(rB.y),         \
                    "r"(rB.z), "r"(rB.w));                                    \
} while (0)

// one k16 step s (0 or 1): 2 A-ldmatrix + 4 B-ldmatrix + 32 MMA
#define COMPUTE_S(buf, s) do {                                                \
    uint32_t ab = (buf), bb = (buf) + A_TILE;                                 \
    uint32_t a[2][4];                                                         \
    _Pragma("unroll") for (int mi = 0; mi < 2; mi++)                          \
        asm volatile("ldmatrix.sync.aligned.m8n8.x4.shared.b16 "              \
                     "{%0,%1,%2,%3}, [%4];"                                   \
                     : "=r"(a[mi][0]), "=r"(a[mi][1]),                        \
                       "=r"(a[mi][2]), "=r"(a[mi][3])                         \
                     : "r"(ab + a_lm + mi * (16 * ROWB) + (s) * 32));         \
    uint32_t b[4][4];                                                         \
    _Pragma("unroll") for (int j = 0; j < 4; j++)                             \
        asm volatile("ldmatrix.sync.aligned.m8n8.x4.shared.b16 "              \
                     "{%0,%1,%2,%3}, [%4];"                                   \
                     : "=r"(b[j][0]), "=r"(b[j][1]),                          \
                       "=r"(b[j][2]), "=r"(b[j][3])                           \
                     : "r"(bb + b_lm + j * (16 * ROWB) + (s) * 32));          \
    _Pragma("unroll") for (int mi = 0; mi < 2; mi++)                          \
        _Pragma("unroll") for (int tn = 0; tn < 8; tn++)                      \
            asm volatile(                                                     \
                "mma.sync.aligned.m16n8k16.row.col.f32.bf16.bf16.f32 "        \
                "{%0,%1,%2,%3}, {%4,%5,%6,%7}, {%8,%9}, {%0,%1,%2,%3};"       \
                : "+f"(acc[mi][tn][0]), "+f"(acc[mi][tn][1]),                 \
                  "+f"(acc[mi][tn][2]), "+f"(acc[mi][tn][3])                  \
                : "r"(a[mi][0]), "r"(a[mi][1]), "r"(a[mi][2]),                \
                  "r"(a[mi][3]),                                              \
                  "r"(b[tn >> 1][(tn & 1) * 2]),                              \
                  "r"(b[tn >> 1][(tn & 1) * 2 + 1]));                         \
} while (0)

#define E1_IDX(j) do {                                                        \
    int o1 = e1base + (j) * 8 + lg;                                           \
    int o2 = o1 + 4;                                                          \
    int o1c = o1 < nobs ? o1 : nobs - 1;                                      \
    int o2c = o2 < nobs ? o2 : nobs - 1;                                      \
    er1 = rows[o1c]; ec1 = cols[o1c]; ev1 = vals[o1c];                        \
    er2 = rows[o2c]; ec2 = cols[o2c]; ev2 = vals[o2c];                        \
} while (0)

#define E1_GATHER(ER, EC) do {                                                \
    ua = *(const uint4*)(g_Ub16 + (size_t)(ER) * RANK + ls * 8);              \
    vb = *(const uint4*)(g_Vt16 + (size_t)(EC) * RANK + ls * 8);              \
} while (0)

#define E1_REDUCE(obase, VV) do {                                             \
    float s_ = 0.f;                                                           \
    const uint32_t* up = &ua.x;                                               \
    const uint32_t* vp = &vb.x;                                               \
    _Pragma("unroll") for (int h = 0; h < 4; h++) {                           \
        float2 fu = __bfloat1622float2(*(const __nv_bfloat162*)&up[h]);       \
        float2 fv = __bfloat1622float2(*(const __nv_bfloat162*)&vp[h]);       \
        s_ = fmaf(fu.x, fv.x, s_);                                            \
        s_ = fmaf(fu.y, fv.y, s_);                                            \
    }                                                                         \
    s_ += __shfl_xor_sync(0xffffffffu, s_, 1);                                \
    s_ += __shfl_xor_sync(0xffffffffu, s_, 2);                                \
    s_ += __shfl_xor_sync(0xffffffffu, s_, 4);                                \
    if (ls == 0 && (obase) + lg < nobs) {                                     \
        float d = (VV) - s_;                                                  \
        e1sum = fmaf(d, d, e1sum);                                            \
    }                                                                         \
} while (0)

    // prologue: chunk 0 staged plainly into buf0
    E1_IDX(0);
    LOAD_A(0, 0);
    STORE_A(buf0, 0);
    LOAD_A(0, 1);
    STORE_A(buf0, 1);
    LOAD_B(0);
    STORE_B(buf0);
    __syncthreads();

    for (int cc = 0; cc < NCH; cc++) {
        uint32_t cur = (cc & 1) ? buf1 : buf0;
        uint32_t nxt = (cc & 1) ? buf0 : buf1;
        size_t ko = (size_t)(cc + 1) * BKC;
        int haveNext = (cc + 1 < NCH);
        // phase 0
        if (haveNext) { LOAD_A(ko, 0); LOAD_B(ko); }
        E1_GATHER(er1, ec1);
        COMPUTE_S(cur, 0);
        E1_REDUCE(e1base + cc * 8, ev1);
        if (haveNext) { STORE_A(nxt, 0); STORE_B(nxt); }
        // phase 1
        if (haveNext) LOAD_A(ko, 1);
        E1_GATHER(er2, ec2);
        COMPUTE_S(cur, 1);
        E1_REDUCE(e1base + cc * 8 + 4, ev2);
        if (haveNext) {
            STORE_A(nxt, 1);
            E1_IDX(cc + 1);
            __syncthreads();
        }
    }

    // quad epilogue: partial = sum of D[row][n] * X[row][n]
    const int g = lane >> 2, tg = lane & 3;
    float partial = 0.f;
    #pragma unroll
    for (int mi = 0; mi < 2; mi++) {
        const int r0 = i0 + wid * 32 + mi * 16 + g;
        #pragma unroll
        for (int tn = 0; tn < 8; tn++) {
            int n = tn * 8 + 2 * tg;
            float2 x0 = *(const float2*)(Xf + (size_t)r0 * RANK + n);
            float2 x1 = *(const float2*)(Xf + (size_t)(r0 + 8) * RANK + n);
            partial = fmaf(acc[mi][tn][0], x0.x, partial);
            partial = fmaf(acc[mi][tn][1], x0.y, partial);
            partial = fmaf(acc[mi][tn][2], x1.x, partial);
            partial = fmaf(acc[mi][tn][3], x1.y, partial);
        }
    }
    #pragma unroll
    for (int o = 16; o; o >>= 1) {
        partial += __shfl_xor_sync(0xffffffffu, partial, o);
        e1sum   += __shfl_xor_sync(0xffffffffu, e1sum, o);
    }
    if (lane == 0) { wsum[wid] = partial; esum[wid] = e1sum; }
    __syncthreads();
    if (t == 0) {
        float s = 0.f, e = 0.f;
        #pragma unroll
        for (int i = 0; i < QTHREADS / 32; i++) { s += wsum[i]; e += esum[i]; }
        atomicAdd(&g_acc[slot], (double)s);
        atomicAdd(&g_acc[0], (double)e);
        __threadfence();
        unsigned int old = atomicAdd(&g_done, 1u);
        if (old == NCTAS - 1) {                  // last CTA finalizes
            __threadfence();
            g_done = 0;                          // reset for next replay
            double e0 = atomicAdd(&g_acc[0], 0.0);
            double e1 = atomicAdd(&g_acc[1], 0.0);
            double e2 = atomicAdd(&g_acc[2], 0.0);
            double s2 = (double)sigma[0] * (double)sigma[0];
            double E = e0 / (2.0 * s2) + 0.5 * (e1 + e2) +
                       (double)nobs * log(s2);
            out[0] = (float)E;
        }
    }
#undef LOAD_A
#undef LOAD_B
#undef STORE_A
#undef STORE_B
#undef COMPUTE_S
#undef E1_IDX
#undef E1_GATHER
#undef E1_REDUCE
}

extern "C" void kernel_launch(void* const* d_in, const int* in_sizes, int n_in,
                              void* d_out, int out_size) {
    const float* vals  = (const float*)d_in[0];
    const int*   rows  = (const int*)d_in[1];
    const int*   cols  = (const int*)d_in[2];
    const float* U     = (const float*)d_in[3];
    const float* V     = (const float*)d_in[4];
    const float* sigma = (const float*)d_in[5];
    const float* S_U   = (const float*)d_in[6];
    const float* S_V   = (const float*)d_in[7];
    int nobs = in_sizes[0];
    float* out = (float*)d_out;

    cudaFuncSetAttribute(fused_kernel,
                         cudaFuncAttributeMaxDynamicSharedMemorySize, QSMEM);

    prep_kernel<<<dim3(NDIM / 32, RANK / 32, 2), dim3(32, 32)>>>(V, U);
    fused_kernel<<<dim3(NDIM / BM, 4, 2), QTHREADS, QSMEM>>>(
        S_U, U, S_V, vals, rows, cols, sigma, out, nobs);
}

// round 15
// speedup vs baseline: 1.5318x; 1.5318x over previous
#include <cuda_runtime.h>
#include <cuda_bf16.h>
#include <cstdint>
#include <math.h>

#define NDIM 8192
#define RANK 64
#define BM 128
#define BKC 64
#define KHALF (NDIM / 2)       // 4096
#define NCHH (KHALF / BKC)     // 64 chunks per CTA
#define QTHREADS 256
#define A_TILE (BM * 144)
#define B_TILE (RANK * 144)
#define QSMEM (1024 + 2 * (A_TILE + B_TILE))
#define NCTAS 256

// ---- device scratch (allocation-free rule) ----
__device__ double g_acc[3];                     // [0]=E1, [1]=quad_U, [2]=quad_V
__device__ unsigned int g_done;                 // CTA completion counter
__device__ float  g_Vt[NDIM * RANK];            // V^T fp32 [8192,64]
__device__ __nv_bfloat16 g_Bu[RANK * NDIM];     // U^T bf16 [64,8192] (MMA B)
__device__ __nv_bfloat16 g_Bv[RANK * NDIM];     // V   bf16 [64,8192] (MMA B)
__device__ __nv_bfloat16 g_Ub16[NDIM * RANK];   // U    bf16 [8192,64] (e1)
__device__ __nv_bfloat16 g_Vt16[NDIM * RANK];   // V^T  bf16 [8192,64] (e1)

__device__ __forceinline__ uint32_t smem_u32(const void* p) {
    uint32_t a;
    asm("{ .reg .u64 t; cvta.to.shared.u64 t, %1; cvt.u32.u64 %0, t; }"
        : "=r"(a) : "l"(p));
    return a;
}

// ======================= prep (fused, grid.z selects) =======================
__global__ void prep_kernel(const float* __restrict__ V,
                            const float* __restrict__ U) {
    __shared__ float tile[32][33];
    if (blockIdx.z == 0) {
        int x = blockIdx.x * 32 + threadIdx.x;   // n
        int y = blockIdx.y * 32 + threadIdx.y;   // r
        float v = V[(size_t)y * NDIM + x];
        tile[threadIdx.y][threadIdx.x] = v;
        g_Bv[(size_t)y * NDIM + x] = __float2bfloat16(v);
        __syncthreads();
        int n = blockIdx.x * 32 + threadIdx.y;
        int r = blockIdx.y * 32 + threadIdx.x;
        float tv = tile[threadIdx.x][threadIdx.y];
        g_Vt[(size_t)n * RANK + r] = tv;
        g_Vt16[(size_t)n * RANK + r] = __float2bfloat16(tv);
        if (blockIdx.x == 0 && blockIdx.y == 0 && threadIdx.y == 0 &&
            threadIdx.x < 3)
            g_acc[threadIdx.x] = 0.0;
    } else {
        int i0 = blockIdx.x * 32, r0 = blockIdx.y * 32;
        float u = U[(size_t)(i0 + threadIdx.y) * RANK + r0 + threadIdx.x];
        tile[threadIdx.y][threadIdx.x] = u;
        g_Ub16[(size_t)(i0 + threadIdx.y) * RANK + r0 + threadIdx.x] =
            __float2bfloat16(u);
        __syncthreads();
        g_Bu[(size_t)(r0 + threadIdx.y) * NDIM + i0 + threadIdx.x] =
            __float2bfloat16(tile[threadIdx.x][threadIdx.y]);
    }
}

// ========= fused quad (HMMA bf16, 32x32 warp tiles) + pipelined e1 =========
// Loop structure = R13 champion (BKC=64, 2 buffers, 1 sync/chunk, e1
// idx-prefetch + gather-over-COMPUTE). Warp tile changed 16x64 -> 32x32
// (wm = wid&3 along M, wn = wid>>2 along N): per k16-step 2 A + 2 B
// ldmatrix instead of 1 + 4 -> 20% less L1 ldmatrix traffic, same regs.
__global__ __launch_bounds__(QTHREADS, 2) void fused_kernel(
    const float* __restrict__ S_U, const float* __restrict__ U,
    const float* __restrict__ S_V, const float* __restrict__ vals,
    const int* __restrict__ rows, const int* __restrict__ cols,
    const float* __restrict__ sigma, float* __restrict__ out, int nobs) {
    extern __shared__ char dynsmem[];
    __shared__ float wsum[QTHREADS / 32];
    __shared__ float esum[QTHREADS / 32];

    const int t = threadIdx.x;
    const int wid = t >> 5, lane = t & 31;
    const int wm = wid & 3, wn = wid >> 2;

    const float* S;
    const __nv_bfloat16* Bg;
    const float* Xf;
    int slot;
    if (blockIdx.z == 0) { S = S_U; Bg = g_Bu; Xf = U;    slot = 1; }
    else                 { S = S_V; Bg = g_Bv; Xf = g_Vt; slot = 2; }
    const int i0 = blockIdx.x * BM;
    const size_t kbase = (size_t)blockIdx.y * KHALF;
    const int ctaid = blockIdx.x + 64 * blockIdx.y + 128 * blockIdx.z; // 0..255

    // e1: warp covers 512 obs; 8 per chunk (2 batches of 4; 8 lanes/obs).
    const int e1base = ctaid * 4096 + wid * 512;
    const int lg = lane >> 3;
    const int ls = lane & 7;

    uint32_t base = (smem_u32(dynsmem) + 1023u) & ~1023u;
    uint32_t buf0 = base;
    uint32_t buf1 = base + (A_TILE + B_TILE);

    // ---- closed-form staging bases (identical to R13) ----
    const float* a_base = S + (size_t)(i0 + (t >> 4)) * NDIM + kbase +
                          (t & 15) * 4;
    const uint32_t a_st = (uint32_t)(t >> 4) * 144 + (t & 15) * 8;
    const __nv_bfloat16* b_base = Bg + (size_t)(t >> 3) * NDIM + kbase +
                                  (t & 7) * 8;
    const uint32_t b_st = (uint32_t)(t >> 3) * 144 + (t & 7) * 16;

    // ldmatrix lane offsets for 32x32 warp tile
    const uint32_t a_lm = (uint32_t)(wm * 32 + (lane & 15)) * 144 +
                          (lane & 16);
    const uint32_t b_lm = (uint32_t)((lane & 7) + ((lane & 16) >> 1) +
                                     wn * 32) * 144 + ((lane & 8) << 1);

    float acc[2][4][4];
    #pragma unroll
    for (int mi = 0; mi < 2; mi++)
        #pragma unroll
        for (int tn = 0; tn < 4; tn++)
            #pragma unroll
            for (int q = 0; q < 4; q++) acc[mi][tn][q] = 0.f;

    float e1sum = 0.f;
    float4 rA[8];
    uint4  rB[2];

    int er1, ec1, er2, ec2;
    float ev1, ev2;
    uint4 ua1, vb1, ua2, vb2;

#define LOADC(k0) do {                                                        \
    _Pragma("unroll") for (int p = 0; p < 8; p++)                             \
        rA[p] = __ldcs((const float4*)(a_base + (k0) +                        \
                                       (size_t)p * 16 * NDIM));               \
    _Pragma("unroll") for (int p = 0; p < 2; p++)                             \
        rB[p] = *(const uint4*)(b_base + (k0) + (size_t)p * 32 * NDIM);       \
} while (0)

#define STOREC(buf) do {                                                      \
    _Pragma("unroll") for (int p = 0; p < 8; p++) {                           \
        uint32_t lo, hi;                                                      \
        asm("cvt.rn.bf16x2.f32 %0, %1, %2;" : "=r"(lo)                        \
            : "f"(rA[p].y), "f"(rA[p].x));                                    \
        asm("cvt.rn.bf16x2.f32 %0, %1, %2;" : "=r"(hi)                        \
            : "f"(rA[p].w), "f"(rA[p].z));                                    \
        asm volatile("st.shared.v2.b32 [%0], {%1, %2};"                       \
                     :: "r"((buf) + a_st + p * (16 * 144)), "r"(lo),          \
                        "r"(hi));                                             \
    }                                                                         \
    _Pragma("unroll") for (int p = 0; p < 2; p++)                             \
        asm volatile("st.shared.v4.b32 [%0], {%1, %2, %3, %4};"               \
                     :: "r"((buf) + A_TILE + b_st + p * (32 * 144)),          \
                        "r"(rB[p].x), "r"(rB[p].y), "r"(rB[p].z),             \
                        "r"(rB[p].w));                                        \
} while (0)

#define COMPUTE(buf) do {                                                     \
    uint32_t ab = (buf), bb = (buf) + A_TILE;                                 \
    _Pragma("unroll") for (int s = 0; s < 4; s++) {                           \
        uint32_t a[2][4];                                                     \
        _Pragma("unroll") for (int mi = 0; mi < 2; mi++)                      \
            asm volatile("ldmatrix.sync.aligned.m8n8.x4.shared.b16 "          \
                         "{%0,%1,%2,%3}, [%4];"                               \
                         : "=r"(a[mi][0]), "=r"(a[mi][1]),                    \
                           "=r"(a[mi][2]), "=r"(a[mi][3])                     \
                         : "r"(ab + a_lm + mi * (16 * 144) + s * 32));        \
        uint32_t b[2][4];                                                     \
        _Pragma("unroll") for (int j = 0; j < 2; j++)                         \
            asm volatile("ldmatrix.sync.aligned.m8n8.x4.shared.b16 "          \
                         "{%0,%1,%2,%3}, [%4];"                               \
                         : "=r"(b[j][0]), "=r"(b[j][1]),                      \
                           "=r"(b[j][2]), "=r"(b[j][3])                       \
                         : "r"(bb + b_lm + j * (16 * 144) + s * 32));         \
        _Pragma("unroll") for (int mi = 0; mi < 2; mi++)                      \
            _Pragma("unroll") for (int tn = 0; tn < 4; tn++)                  \
                asm volatile(                                                 \
                    "mma.sync.aligned.m16n8k16.row.col.f32.bf16.bf16.f32 "    \
                    "{%0,%1,%2,%3}, {%4,%5,%6,%7}, {%8,%9}, {%0,%1,%2,%3};"   \
                    : "+f"(acc[mi][tn][0]), "+f"(acc[mi][tn][1]),             \
                      "+f"(acc[mi][tn][2]), "+f"(acc[mi][tn][3])              \
                    : "r"(a[mi][0]), "r"(a[mi][1]), "r"(a[mi][2]),            \
                      "r"(a[mi][3]),                                          \
                      "r"(b[tn >> 1][(tn & 1) * 2]),                          \
                      "r"(b[tn >> 1][(tn & 1) * 2 + 1]));                     \
    }                                                                         \
} while (0)

#define E1_IDX(j) do {                                                        \
    int o1 = e1base + (j) * 8 + lg;                                           \
    int o2 = o1 + 4;                                                          \
    int o1c = o1 < nobs ? o1 : nobs - 1;                                      \
    int o2c = o2 < nobs ? o2 : nobs - 1;                                      \
    er1 = rows[o1c]; ec1 = cols[o1c]; ev1 = vals[o1c];                        \
    er2 = rows[o2c]; ec2 = cols[o2c]; ev2 = vals[o2c];                        \
} while (0)

#define E1_GATHER() do {                                                      \
    ua1 = *(const uint4*)(g_Ub16 + (size_t)er1 * RANK + ls * 8);              \
    vb1 = *(const uint4*)(g_Vt16 + (size_t)ec1 * RANK + ls * 8);              \
    ua2 = *(const uint4*)(g_Ub16 + (size_t)er2 * RANK + ls * 8);              \
    vb2 = *(const uint4*)(g_Vt16 + (size_t)ec2 * RANK + ls * 8);              \
} while (0)

#define E1_DOT(UA, VB, OUT) do {                                              \
    float s_ = 0.f;                                                           \
    const uint32_t* up = &(UA).x;                                             \
    const uint32_t* vp = &(VB).x;                                             \
    _Pragma("unroll") for (int h = 0; h < 4; h++) {                           \
        float2 fu = __bfloat1622float2(*(const __nv_bfloat162*)&up[h]);       \
        float2 fv = __bfloat1622float2(*(const __nv_bfloat162*)&vp[h]);       \
        s_ = fmaf(fu.x, fv.x, s_);                                            \
        s_ = fmaf(fu.y, fv.y, s_);                                            \
    }                                                                         \
    s_ += __shfl_xor_sync(0xffffffffu, s_, 1);                                \
    s_ += __shfl_xor_sync(0xffffffffu, s_, 2);                                \
    s_ += __shfl_xor_sync(0xffffffffu, s_, 4);                                \
    OUT = s_;                                                                 \
} while (0)

#define E1_REDUCE(j, vv1, vv2) do {                                           \
    float p1, p2;                                                             \
    E1_DOT(ua1, vb1, p1);                                                     \
    E1_DOT(ua2, vb2, p2);                                                     \
    if (ls == 0) {                                                            \
        int o1 = e1base + (j) * 8 + lg;                                       \
        if (o1 < nobs) {                                                      \
            float d = (vv1) - p1;                                             \
            e1sum = fmaf(d, d, e1sum);                                        \
        }                                                                     \
        if (o1 + 4 < nobs) {                                                  \
            float d = (vv2) - p2;                                             \
            e1sum = fmaf(d, d, e1sum);                                        \
        }                                                                     \
    }                                                                         \
} while (0)

    // prologue
    E1_IDX(0);
    LOADC(0);
    STOREC(buf0);
    __syncthreads();

    // steady: load(cc+1) | e1 gathers | idx prefetch(cc+1) | compute(cc) |
    //         e1 reduce(cc) | store(cc+1) | 1 sync
    for (int cc = 0; cc < NCHH; cc++) {
        uint32_t cur = (cc & 1) ? buf1 : buf0;
        uint32_t nxt = (cc & 1) ? buf0 : buf1;
        if (cc + 1 < NCHH) LOADC((size_t)(cc + 1) * BKC);
        E1_GATHER();
        float vv1 = ev1, vv2 = ev2;
        if (cc + 1 < NCHH) E1_IDX(cc + 1);
        COMPUTE(cur);
        E1_REDUCE(cc, vv1, vv2);
        if (cc + 1 < NCHH) {
            STOREC(nxt);
            __syncthreads();
        }
    }

    // quad epilogue: partial = sum of D[row][n] * X[row][n]
    const int g = lane >> 2, tg = lane & 3;
    float partial = 0.f;
    #pragma unroll
    for (int mi = 0; mi < 2; mi++) {
        const int r0 = i0 + wm * 32 + mi * 16 + g;
        #pragma unroll
        for (int tn = 0; tn < 4; tn++) {
            int n = wn * 32 + tn * 8 + 2 * tg;
            float2 x0 = *(const float2*)(Xf + (size_t)r0 * RANK + n);
            float2 x1 = *(const float2*)(Xf + (size_t)(r0 + 8) * RANK + n);
            partial = fmaf(acc[mi][tn][0], x0.x, partial);
            partial = fmaf(acc[mi][tn][1], x0.y, partial);
            partial = fmaf(acc[mi][tn][2], x1.x, partial);
            partial = fmaf(acc[mi][tn][3], x1.y, partial);
        }
    }
    #pragma unroll
    for (int o = 16; o; o >>= 1) {
        partial += __shfl_xor_sync(0xffffffffu, partial, o);
        e1sum   += __shfl_xor_sync(0xffffffffu, e1sum, o);
    }
    if (lane == 0) { wsum[wid] = partial; esum[wid] = e1sum; }
    __syncthreads();
    if (t == 0) {
        float s = 0.f, e = 0.f;
        #pragma unroll
        for (int i = 0; i < QTHREADS / 32; i++) { s += wsum[i]; e += esum[i]; }
        atomicAdd(&g_acc[slot], (double)s);
        atomicAdd(&g_acc[0], (double)e);
        __threadfence();
        unsigned int old = atomicAdd(&g_done, 1u);
        if (old == NCTAS - 1) {                  // last CTA finalizes
            __threadfence();
            g_done = 0;                          // reset for next replay
            double e0 = atomicAdd(&g_acc[0], 0.0);
            double e1 = atomicAdd(&g_acc[1], 0.0);
            double e2 = atomicAdd(&g_acc[2], 0.0);
            double s2 = (double)sigma[0] * (double)sigma[0];
            double E = e0 / (2.0 * s2) + 0.5 * (e1 + e2) +
                       (double)nobs * log(s2);
            out[0] = (float)E;
        }
    }
#undef LOADC
#undef STOREC
#undef COMPUTE
#undef E1_IDX
#undef E1_GATHER
#undef E1_DOT
#undef E1_REDUCE
}

extern "C" void kernel_launch(void* const* d_in, const int* in_sizes, int n_in,
                              void* d_out, int out_size) {
    const float* vals  = (const float*)d_in[0];
    const int*   rows  = (const int*)d_in[1];
    const int*   cols  = (const int*)d_in[2];
    const float* U     = (const float*)d_in[3];
    const float* V     = (const float*)d_in[4];
    const float* sigma = (const float*)d_in[5];
    const float* S_U   = (const float*)d_in[6];
    const float* S_V   = (const float*)d_in[7];
    int nobs = in_sizes[0];
    float* out = (float*)d_out;

    cudaFuncSetAttribute(fused_kernel,
                         cudaFuncAttributeMaxDynamicSharedMemorySize, QSMEM);

    prep_kernel<<<dim3(NDIM / 32, RANK / 32, 2), dim3(32, 32)>>>(V, U);
    fused_kernel<<<dim3(NDIM / BM, 2, 2), QTHREADS, QSMEM>>>(
        S_U, U, S_V, vals, rows, cols, sigma, out, nobs);
}